// round 14
// baseline (speedup 1.0000x reference)
#include <cuda_runtime.h>

// Gaussian-splat over-compositing, N pixels x K gaussians, sm_103a.
// R14: hybrid loop, 2 px/thread.
//  - Quadratic form computed PACKED (f32x2): inputs packed once in prologue,
//    constants stored as duplicated pairs in smem, result unpacked for free
//    (pair halves are just registers). 5 fma2 instead of 10 FFMA.
//  - Compositing stays SCALAR per pixel (no pack movs):
//      e = ex2(q);  w = fma(-d, e, e)          // e*(1-d), d = pa+eps
//      u_c = fma(u_c, g, col_c*w); d += w; r = rcp(d); g = fma(r,-eps,1)
//  Final: pa = d-eps; pc = u*r_last.  Exact reference semantics (~1ulp/step).

#define MAXK 128
#define EPSC 1e-8f

typedef unsigned long long u64;

__device__ __forceinline__ u64 pack2(float a, float b) {
    u64 r; asm("mov.b64 %0, {%1, %2};" : "=l"(r) : "f"(a), "f"(b)); return r;
}
__device__ __forceinline__ void unpack2(u64 v, float& a, float& b) {
    asm("mov.b64 {%0, %1}, %2;" : "=f"(a), "=f"(b) : "l"(v));
}
__device__ __forceinline__ u64 fma2(u64 a, u64 b, u64 c) {
    u64 d; asm("fma.rn.f32x2 %0, %1, %2, %3;" : "=l"(d) : "l"(a), "l"(b), "l"(c)); return d;
}
__device__ __forceinline__ u64 mul2(u64 a, u64 b) {
    u64 d; asm("mul.rn.f32x2 %0, %1, %2;" : "=l"(d) : "l"(a), "l"(b)); return d;
}
__device__ __forceinline__ float ex2f_(float x) {
    float y; asm("ex2.approx.f32 %0, %1;" : "=f"(y) : "f"(x)); return y;
}
__device__ __forceinline__ float rcpf_(float x) {
    float y; asm("rcp.approx.f32 %0, %1;" : "=f"(y) : "f"(x)); return y;
}

// smem layout per k (64 B, 4x float4):
//  [0] = {A, A, B2, B2}   [1] = {C, C, Dx, Dx}
//  [2] = {Ey, Ey, F, F}   [3] = {c0, c1, c2, 0}
__device__ __forceinline__ void prep_params(float4* sp4,
                                            const float* mu, const float* alpha,
                                            const float* color, const float* scales,
                                            const float* thetas, int K) {
    const float L2E = 1.44269504088896340736f;
    for (int k = threadIdx.x; k < K; k += blockDim.x) {
        float th = thetas[k];
        float c = cosf(th), s = sinf(th);
        float sx = fmaxf(scales[2 * k + 0], 0.1f);
        float sy = fmaxf(scales[2 * k + 1], 0.1f);
        float ix = 1.0f / (sx * sx);
        float iy = 1.0f / (sy * sy);
        float S00 = c * c * ix + s * s * iy;
        float S01 = c * s * (ix - iy);
        float S11 = s * s * ix + c * c * iy;
        float h = -0.5f * L2E;
        float A  = h * S00;
        float B2 = (2.0f * h) * S01;
        float C  = h * S11;
        float a  = fminf(fmaxf(alpha[k], 0.0f), 1.0f);
        float la = log2f(fmaxf(a, 1e-38f));
        float c0 = fminf(fmaxf(color[3 * k + 0], 0.0f), 255.0f);
        float c1 = fminf(fmaxf(color[3 * k + 1], 0.0f), 255.0f);
        float c2 = fminf(fmaxf(color[3 * k + 2], 0.0f), 255.0f);
        float mx = mu[2 * k + 0] - 256.0f;   // centered coords
        float my = mu[2 * k + 1] - 256.0f;
        float Dx = -(2.0f * A * mx + B2 * my);
        float Ey = -(B2 * mx + 2.0f * C * my);
        float F  = (A * mx * mx + B2 * mx * my + C * my * my) + la;
        sp4[k * 4 + 0] = make_float4(A, A, B2, B2);
        sp4[k * 4 + 1] = make_float4(C, C, Dx, Dx);
        sp4[k * 4 + 2] = make_float4(Ey, Ey, F, F);
        sp4[k * 4 + 3] = make_float4(c0, c1, c2, 0.0f);
    }
}

template<int KT>
__global__ __launch_bounds__(64)
void gs_splat_kernel(const float* __restrict__ pos,
                     const float* __restrict__ mu,
                     const float* __restrict__ alpha,
                     const float* __restrict__ color,
                     const float* __restrict__ scales,
                     const float* __restrict__ thetas,
                     float4* __restrict__ out,
                     int n, int K)
{
    const int KK = (KT > 0) ? KT : K;
    __shared__ __align__(16) float4 sp4[MAXK * 4];
    prep_params(sp4, mu, alpha, color, scales, thetas, K);
    __syncthreads();

    int base = blockIdx.x * ((int)blockDim.x * 2);
    int i0 = base + threadIdx.x;
    int i1 = i0 + blockDim.x;
    bool v0 = (i0 < n), v1 = (i1 < n);
    const float2* pos2 = (const float2*)pos;
    float2 P0 = v0 ? pos2[i0] : make_float2(0.0f, 0.0f);
    float2 P1 = v1 ? pos2[i1] : make_float2(0.0f, 0.0f);

    // packed monomials, built ONCE (pack movs outside loop)
    float x0 = P0.x - 256.0f, y0 = P0.y - 256.0f;
    float x1 = P1.x - 256.0f, y1 = P1.y - 256.0f;
    u64 X  = pack2(x0, x1);
    u64 Y  = pack2(y0, y1);
    u64 X2 = mul2(X, X);
    u64 XY = mul2(X, Y);
    u64 Y2 = mul2(Y, Y);

    // scalar compositing state per pixel
    float u00 = 0.0f, u10 = 0.0f, u20 = 0.0f;   // px0 numerators
    float u01 = 0.0f, u11 = 0.0f, u21 = 0.0f;   // px1 numerators
    float d0 = EPSC, d1 = EPSC;                  // pa + eps
    float g0 = 0.0f, g1 = 0.0f;                  // carry pa/(pa+eps)
    float r0 = 0.0f, r1 = 0.0f;                  // last rcp

    const ulonglong2* __restrict__ gp = (const ulonglong2*)sp4;

#pragma unroll 8
    for (int k = 0; k < KK; k++) {
        ulonglong2 q0 = gp[k * 2 + 0];           // {A2, B22}, {C2, Dx2}... wait:
        // gp stride: 64B per k = 2 ulonglong2 of pairs + 1 float4 colors.
        // Recompute: sp4[k*4+0..2] are pairs (3 float4 = 24B? no 48B), +3 colors.
        ulonglong2 qa = *(const ulonglong2*)&sp4[k * 4 + 0]; // {A2, B22}
        ulonglong2 qb = *(const ulonglong2*)&sp4[k * 4 + 1]; // {C2, Dx2}
        ulonglong2 qc = *(const ulonglong2*)&sp4[k * 4 + 2]; // {Ey2, F2}
        float4 col    = sp4[k * 4 + 3];
        (void)q0;

        u64 t = fma2(qc.x, Y, qc.y);             // Ey*y + F
        t = fma2(qb.y, X, t);                    // + Dx*x
        t = fma2(qb.x, Y2, t);                   // + C*y2
        t = fma2(qa.y, XY, t);                   // + B2*xy
        u64 q = fma2(qa.x, X2, t);               // + A*x2

        float qf0, qf1; unpack2(q, qf0, qf1);    // free: pair halves

        // pixel 0 (scalar)
        float e0 = ex2f_(qf0);
        float w0 = fmaf(-d0, e0, e0);            // e*(1-d)
        u00 = fmaf(u00, g0, col.x * w0);
        u10 = fmaf(u10, g0, col.y * w0);
        u20 = fmaf(u20, g0, col.z * w0);
        d0 += w0;
        r0 = rcpf_(d0);
        g0 = fmaf(r0, -EPSC, 1.0f);

        // pixel 1 (scalar)
        float e1 = ex2f_(qf1);
        float w1 = fmaf(-d1, e1, e1);
        u01 = fmaf(u01, g1, col.x * w1);
        u11 = fmaf(u11, g1, col.y * w1);
        u21 = fmaf(u21, g1, col.z * w1);
        d1 += w1;
        r1 = rcpf_(d1);
        g1 = fmaf(r1, -EPSC, 1.0f);
    }

    if (v0) {
        float pa = d0 - EPSC;
        out[i0] = make_float4(fminf(fmaxf(u00 * r0, 0.0f), 255.0f),
                              fminf(fmaxf(u10 * r0, 0.0f), 255.0f),
                              fminf(fmaxf(u20 * r0, 0.0f), 255.0f),
                              fminf(fmaxf(pa, 0.0f), 1.0f) * 255.0f);
    }
    if (v1) {
        float pa = d1 - EPSC;
        out[i1] = make_float4(fminf(fmaxf(u01 * r1, 0.0f), 255.0f),
                              fminf(fmaxf(u11 * r1, 0.0f), 255.0f),
                              fminf(fmaxf(u21 * r1, 0.0f), 255.0f),
                              fminf(fmaxf(pa, 0.0f), 1.0f) * 255.0f);
    }
}

extern "C" void kernel_launch(void* const* d_in, const int* in_sizes, int n_in,
                              void* d_out, int out_size)
{
    const float* pos    = (const float*)d_in[0];
    const float* mu     = (const float*)d_in[1];
    const float* alpha  = (const float*)d_in[2];
    const float* color  = (const float*)d_in[3];
    const float* scales = (const float*)d_in[4];
    const float* thetas = (const float*)d_in[5];

    int n = in_sizes[0] / 2;     // pixels
    int K = in_sizes[2];         // gaussians
    if (K > MAXK) K = MAXK;

    const int threads = 64;
    const int pixPerCta = threads * 2;   // 128 pixels per block
    int grid = (n + pixPerCta - 1) / pixPerCta;

    if (K == 128) {
        gs_splat_kernel<128><<<grid, threads>>>(pos, mu, alpha, color, scales,
                                                thetas, (float4*)d_out, n, K);
    } else {
        gs_splat_kernel<0><<<grid, threads>>>(pos, mu, alpha, color, scales,
                                              thetas, (float4*)d_out, n, K);
    }
}

// round 15
// speedup vs baseline: 1.0539x; 1.0539x over previous
#include <cuda_runtime.h>

// Gaussian-splat over-compositing, N pixels x K gaussians, sm_103a.
// R15: scalar loop (R13 skeleton, passed @2.9e-6), 2 px/thread to amortize
// LDS + loop overhead and double ILP. No f32x2 packing anywhere.
// Per px-step:
//   q = A x2 + B2 xy + C y2 + Dx x + Ey y + F     (5 FMA, monomials cached)
//   e = ex2(q);  w = fma(-d, e, e)                // e*(1-d), d = pa+eps
//   u_c = fma(u_c, g, col_c*w)   (3 channels)
//   d += w;  r = rcp(d);  g = fma(r, -eps, 1)     // pa/(pa+eps)
// Final: pa = d-eps; pc = u*r_last. Exact reference semantics (~1ulp/step).

#define MAXK 128
#define EPSC 1e-8f

__device__ __forceinline__ float ex2f_(float x) {
    float y; asm("ex2.approx.f32 %0, %1;" : "=f"(y) : "f"(x)); return y;
}
__device__ __forceinline__ float rcpf_(float x) {
    float y; asm("rcp.approx.f32 %0, %1;" : "=f"(y) : "f"(x)); return y;
}

// layout per k: [A, B2, C, Dx] [Ey, F, c0, c1] [c2, 0, 0, 0]  (3 x float4)
__device__ __forceinline__ void prep_params(float4* sp4,
                                            const float* mu, const float* alpha,
                                            const float* color, const float* scales,
                                            const float* thetas, int K) {
    const float L2E = 1.44269504088896340736f;
    for (int k = threadIdx.x; k < K; k += blockDim.x) {
        float th = thetas[k];
        float c = cosf(th), s = sinf(th);
        float sx = fmaxf(scales[2 * k + 0], 0.1f);
        float sy = fmaxf(scales[2 * k + 1], 0.1f);
        float ix = 1.0f / (sx * sx);
        float iy = 1.0f / (sy * sy);
        float S00 = c * c * ix + s * s * iy;
        float S01 = c * s * (ix - iy);
        float S11 = s * s * ix + c * c * iy;
        float h = -0.5f * L2E;
        float A  = h * S00;
        float B2 = (2.0f * h) * S01;
        float C  = h * S11;
        float a  = fminf(fmaxf(alpha[k], 0.0f), 1.0f);
        float la = log2f(fmaxf(a, 1e-38f));
        float c0 = fminf(fmaxf(color[3 * k + 0], 0.0f), 255.0f);
        float c1 = fminf(fmaxf(color[3 * k + 1], 0.0f), 255.0f);
        float c2 = fminf(fmaxf(color[3 * k + 2], 0.0f), 255.0f);
        float mx = mu[2 * k + 0] - 256.0f;   // centered coords
        float my = mu[2 * k + 1] - 256.0f;
        float Dx = -(2.0f * A * mx + B2 * my);
        float Ey = -(B2 * mx + 2.0f * C * my);
        float F  = (A * mx * mx + B2 * mx * my + C * my * my) + la;
        sp4[k * 3 + 0] = make_float4(A, B2, C, Dx);
        sp4[k * 3 + 1] = make_float4(Ey, F, c0, c1);
        sp4[k * 3 + 2] = make_float4(c2, 0.0f, 0.0f, 0.0f);
    }
}

template<int KT>
__global__ __launch_bounds__(128)
void gs_splat_kernel(const float* __restrict__ pos,
                     const float* __restrict__ mu,
                     const float* __restrict__ alpha,
                     const float* __restrict__ color,
                     const float* __restrict__ scales,
                     const float* __restrict__ thetas,
                     float4* __restrict__ out,
                     int n, int K)
{
    const int KK = (KT > 0) ? KT : K;
    __shared__ __align__(16) float4 sp4[MAXK * 3];
    prep_params(sp4, mu, alpha, color, scales, thetas, K);
    __syncthreads();

    int base = blockIdx.x * ((int)blockDim.x * 2);
    int i0 = base + threadIdx.x;
    int i1 = i0 + blockDim.x;
    bool v0 = (i0 < n), v1 = (i1 < n);
    const float2* pos2 = (const float2*)pos;
    float2 P0 = v0 ? pos2[i0] : make_float2(0.0f, 0.0f);
    float2 P1 = v1 ? pos2[i1] : make_float2(0.0f, 0.0f);

    // per-pixel monomials (registers)
    float X0 = P0.x - 256.0f, Y0 = P0.y - 256.0f;
    float X1 = P1.x - 256.0f, Y1 = P1.y - 256.0f;
    float X20 = X0 * X0, XY0 = X0 * Y0, Y20 = Y0 * Y0;
    float X21 = X1 * X1, XY1 = X1 * Y1, Y21 = Y1 * Y1;

    // scalar compositing state per pixel
    float u00 = 0.0f, u10 = 0.0f, u20 = 0.0f;
    float u01 = 0.0f, u11 = 0.0f, u21 = 0.0f;
    float d0 = EPSC, d1 = EPSC;                  // pa + eps
    float g0 = 0.0f, g1 = 0.0f;                  // carry pa/(pa+eps)
    float r0 = 0.0f, r1 = 0.0f;                  // last rcp

#pragma unroll 8
    for (int k = 0; k < KK; k++) {
        float4 p0 = sp4[k * 3 + 0];   // A, B2, C, Dx
        float4 p1 = sp4[k * 3 + 1];   // Ey, F, c0, c1
        float4 p2 = sp4[k * 3 + 2];   // c2, -, -, -

        // pixel 0 quad
        float t0 = fmaf(p1.x, Y0, p1.y);
        t0 = fmaf(p0.w, X0, t0);
        t0 = fmaf(p0.z, Y20, t0);
        t0 = fmaf(p0.y, XY0, t0);
        float q0 = fmaf(p0.x, X20, t0);
        // pixel 1 quad
        float t1 = fmaf(p1.x, Y1, p1.y);
        t1 = fmaf(p0.w, X1, t1);
        t1 = fmaf(p0.z, Y21, t1);
        t1 = fmaf(p0.y, XY1, t1);
        float q1 = fmaf(p0.x, X21, t1);

        float e0 = ex2f_(q0);
        float e1 = ex2f_(q1);

        // pixel 0 composite
        float w0 = fmaf(-d0, e0, e0);
        u00 = fmaf(u00, g0, p1.z * w0);
        u10 = fmaf(u10, g0, p1.w * w0);
        u20 = fmaf(u20, g0, p2.x * w0);
        d0 += w0;
        r0 = rcpf_(d0);
        g0 = fmaf(r0, -EPSC, 1.0f);

        // pixel 1 composite
        float w1 = fmaf(-d1, e1, e1);
        u01 = fmaf(u01, g1, p1.z * w1);
        u11 = fmaf(u11, g1, p1.w * w1);
        u21 = fmaf(u21, g1, p2.x * w1);
        d1 += w1;
        r1 = rcpf_(d1);
        g1 = fmaf(r1, -EPSC, 1.0f);
    }

    if (v0) {
        float pa = d0 - EPSC;
        out[i0] = make_float4(fminf(fmaxf(u00 * r0, 0.0f), 255.0f),
                              fminf(fmaxf(u10 * r0, 0.0f), 255.0f),
                              fminf(fmaxf(u20 * r0, 0.0f), 255.0f),
                              fminf(fmaxf(pa, 0.0f), 1.0f) * 255.0f);
    }
    if (v1) {
        float pa = d1 - EPSC;
        out[i1] = make_float4(fminf(fmaxf(u01 * r1, 0.0f), 255.0f),
                              fminf(fmaxf(u11 * r1, 0.0f), 255.0f),
                              fminf(fmaxf(u21 * r1, 0.0f), 255.0f),
                              fminf(fmaxf(pa, 0.0f), 1.0f) * 255.0f);
    }
}

extern "C" void kernel_launch(void* const* d_in, const int* in_sizes, int n_in,
                              void* d_out, int out_size)
{
    const float* pos    = (const float*)d_in[0];
    const float* mu     = (const float*)d_in[1];
    const float* alpha  = (const float*)d_in[2];
    const float* color  = (const float*)d_in[3];
    const float* scales = (const float*)d_in[4];
    const float* thetas = (const float*)d_in[5];

    int n = in_sizes[0] / 2;     // pixels
    int K = in_sizes[2];         // gaussians
    if (K > MAXK) K = MAXK;

    const int threads = 128;
    const int pixPerCta = threads * 2;   // 256 pixels per block
    int grid = (n + pixPerCta - 1) / pixPerCta;

    if (K == 128) {
        gs_splat_kernel<128><<<grid, threads>>>(pos, mu, alpha, color, scales,
                                                thetas, (float4*)d_out, n, K);
    } else {
        gs_splat_kernel<0><<<grid, threads>>>(pos, mu, alpha, color, scales,
                                              thetas, (float4*)d_out, n, K);
    }
}